// round 7
// baseline (speedup 1.0000x reference)
#include <cuda_runtime.h>
#include <cuda_bf16.h>
#include <math.h>
#include <stdint.h>

// Problem constants
#define BB 2
#define TT 2048
#define DM 2048
#define NH 32
#define NKV 8
#define HD 64
#define MROWS (BB*TT)          // 4096
#define QN (NH*HD)             // 2048
#define KN (NKV*HD)            // 512
#define GK DM                  // K dim of every GEMM = 2048

// Scratch (device globals — allocation-free)
__device__ float g_q[MROWS*QN];
__device__ float g_k[MROWS*KN];
__device__ float g_v[MROWS*KN];
__device__ float g_att[MROWS*QN];
__device__ float g_xc[MROWS*DM];
__device__ float g_wqc[QN*DM];
__device__ float g_wkc[KN*DM];
__device__ float g_wvc[KN*DM];
__device__ float g_woc[DM*QN];

__device__ __forceinline__ float rna(float x) {
    uint32_t u;
    asm("cvt.rna.tf32.f32 %0, %1;" : "=r"(u) : "f"(x));
    return __uint_as_float(u);
}
__device__ __forceinline__ uint32_t smem_u32(const void* p) {
    uint32_t a;
    asm("{ .reg .u64 t; cvta.to.shared.u64 t, %1; cvt.u32.u64 %0, t; }"
        : "=r"(a) : "l"(p));
    return a;
}
__device__ __forceinline__ void mma_tf32(float c[4], const uint32_t a[4],
                                         const uint32_t b[2]) {
    asm volatile(
        "mma.sync.aligned.m16n8k8.row.col.f32.tf32.tf32.f32 "
        "{%0,%1,%2,%3}, {%4,%5,%6,%7}, {%8,%9}, {%0,%1,%2,%3};"
        : "+f"(c[0]), "+f"(c[1]), "+f"(c[2]), "+f"(c[3])
        : "r"(a[0]), "r"(a[1]), "r"(a[2]), "r"(a[3]), "r"(b[0]), "r"(b[1]));
}

// ---------------------------------------------------------------------------
// tf32 rounding pass
// ---------------------------------------------------------------------------
__global__ void cvt_tf32(const float* __restrict__ in, float* __restrict__ out, int n4) {
    int i = blockIdx.x * blockDim.x + threadIdx.x;
    if (i >= n4) return;
    float4 v = ((const float4*)in)[i];
    ((float4*)out)[i] = make_float4(rna(v.x), rna(v.y), rna(v.z), rna(v.w));
}

// ---------------------------------------------------------------------------
// mma.sync tf32 NT GEMM, BM=128, BN=256, BK=32, 256 threads.
// Inputs pre-rounded to tf32; fragment loads are plain LDS.
// Segmented-N for fused QKV (see R5).
// ---------------------------------------------------------------------------
#define BM 128
#define BN 256
#define BK 32
#define NCH (GK/BK)            // 64
#define RST 36
#define ATILEB (128*RST*4)
#define STAGEB ((128+256)*RST*4)
#define GEMM_SMEM (2*STAGEB)   // 110592 B

__global__ __launch_bounds__(256, 1) void gemm_mma(
    const float* __restrict__ A,
    const float* __restrict__ B0, const float* __restrict__ B1,
    const float* __restrict__ B2,
    float* __restrict__ C0, float* __restrict__ C1, float* __restrict__ C2,
    int nb1, int nb2, int ld0) {
    extern __shared__ float sm[];
    const int tid = threadIdx.x;
    const int bm = blockIdx.y * BM;
    const int bn = blockIdx.x * BN;
    const int wid = tid >> 5, lane = tid & 31;
    const int g = lane >> 2, tg = lane & 3;
    const int wm = (wid >> 2) * 64;
    const int wn = (wid & 3) * 64;

    const float* Bp; float* Cp; int nb, ldc;
    if (bn < nb1)      { Bp = B0; Cp = C0; nb = bn;       ldc = ld0; }
    else if (bn < nb2) { Bp = B1; Cp = C1; nb = bn - nb1; ldc = 512; }
    else               { Bp = B2; Cp = C2; nb = bn - nb2; ldc = 512; }

    float c[4][8][4];
#pragma unroll
    for (int i = 0; i < 4; i++)
#pragma unroll
        for (int j = 0; j < 8; j++)
#pragma unroll
            for (int q = 0; q < 4; q++) c[i][j][q] = 0.f;

    const uint32_t sb = smem_u32(sm);

    auto load_chunk = [&](int kc, int s) {
        uint32_t base = sb + s * STAGEB;
#pragma unroll
        for (int j = 0; j < 12; j++) {
            int u = tid + j * 256;
            uint32_t sa;
            const float* gp;
            if (u < 1024) {
                int r = u >> 3, c16 = u & 7;
                sa = base + r * (RST*4) + c16 * 16;
                gp = A + (size_t)(bm + r) * GK + kc * BK + c16 * 4;
            } else {
                int uu = u - 1024;
                int r = uu >> 3, c16 = uu & 7;
                sa = base + ATILEB + r * (RST*4) + c16 * 16;
                gp = Bp + (size_t)(nb + r) * GK + kc * BK + c16 * 4;
            }
            asm volatile("cp.async.cg.shared.global [%0], [%1], 16;"
                         :: "r"(sa), "l"(gp));
        }
        asm volatile("cp.async.commit_group;" ::: "memory");
    };

    load_chunk(0, 0);

    for (int t = 0; t < NCH; t++) {
        const int s = t & 1;
        if (t + 1 < NCH) {
            load_chunk(t + 1, (t + 1) & 1);
            asm volatile("cp.async.wait_group 1;" ::: "memory");
        } else {
            asm volatile("cp.async.wait_group 0;" ::: "memory");
        }
        __syncthreads();

        const float* Ab = sm + s * (STAGEB/4);
        const float* Bb = Ab + ATILEB/4;
#pragma unroll
        for (int ks = 0; ks < 4; ks++) {
            const int k0 = ks * 8;
            uint32_t af[4][4], bf[8][2];
#pragma unroll
            for (int tm = 0; tm < 4; tm++) {
                const int m0 = wm + tm * 16;
                af[tm][0] = __float_as_uint(Ab[(m0 + g)     * RST + k0 + tg]);
                af[tm][1] = __float_as_uint(Ab[(m0 + g + 8) * RST + k0 + tg]);
                af[tm][2] = __float_as_uint(Ab[(m0 + g)     * RST + k0 + tg + 4]);
                af[tm][3] = __float_as_uint(Ab[(m0 + g + 8) * RST + k0 + tg + 4]);
            }
#pragma unroll
            for (int tn = 0; tn < 8; tn++) {
                const int n0 = wn + tn * 8;
                bf[tn][0] = __float_as_uint(Bb[(n0 + g) * RST + k0 + tg]);
                bf[tn][1] = __float_as_uint(Bb[(n0 + g) * RST + k0 + tg + 4]);
            }
#pragma unroll
            for (int tm = 0; tm < 4; tm++)
#pragma unroll
                for (int tn = 0; tn < 8; tn++)
                    mma_tf32(c[tm][tn], af[tm], bf[tn]);
        }
        __syncthreads();
    }

#pragma unroll
    for (int tm = 0; tm < 4; tm++) {
        const int row0 = bm + wm + tm * 16 + g;
#pragma unroll
        for (int tn = 0; tn < 8; tn++) {
            const int col = nb + wn + tn * 8 + tg * 2;
            *(float2*)&Cp[(size_t)row0 * ldc + col] =
                make_float2(c[tm][tn][0], c[tm][tn][1]);
            *(float2*)&Cp[(size_t)(row0 + 8) * ldc + col] =
                make_float2(c[tm][tn][2], c[tm][tn][3]);
        }
    }
}

// ---------------------------------------------------------------------------
// RoPE (in-place)
// ---------------------------------------------------------------------------
__global__ void rope_kernel(float* __restrict__ x, const float* __restrict__ cs,
                            const float* __restrict__ sn, int nheads, int total) {
    int idx = blockIdx.x * blockDim.x + threadIdx.x;
    if (idx >= total) return;
    int d  = idx & 31;
    int h  = (idx >> 5) % nheads;
    int bt = idx / (32 * nheads);
    int t  = bt & (TT - 1);
    float* row = x + (size_t)bt * (nheads * HD) + h * HD;
    float x1 = row[d], x2 = row[d + 32];
    float c1 = cs[t * HD + d],      s1 = sn[t * HD + d];
    float c2 = cs[t * HD + d + 32], s2 = sn[t * HD + d + 32];
    row[d]      = x1 * c1 - x2 * s1;
    row[d + 32] = x2 * c2 + x1 * s2;
}

// ---------------------------------------------------------------------------
// Tensor-core flash attention v2 (tf32 mma.sync), causal, GQA
// Block: 128 threads (4 warps x 32 q-rows). Tiles: 128 q x 64 kv, HD=64.
// Each B-fragment feeds two A-fragments (lo/hi 16-row halves).
// Smem: Ks[64][68], Vs[64][72], Ps[128][68] = 70656 B.
// Output written tf32-rounded (consumed by O-proj GEMM directly).
// ---------------------------------------------------------------------------
#define KST 68
#define VST 72
#define ATTN_SMEM ((64*KST + 64*VST + 128*KST) * 4)

__global__ __launch_bounds__(128) void attn_tc(const float* __restrict__ q,
                                               const float* __restrict__ k,
                                               const float* __restrict__ v,
                                               float* __restrict__ o) {
    const int qt = (int)gridDim.x - 1 - (int)blockIdx.x;   // heavy CTAs first
    const int h  = blockIdx.y;
    const int b  = blockIdx.z;
    const int kvh = h >> 2;
    const int q0 = qt * 128;

    extern __shared__ float sm[];
    float* Ks = sm;                    // [64][KST]
    float* Vs = Ks + 64 * KST;         // [64][VST]
    float* Ps = Vs + 64 * VST;         // [128][KST]

    const int tid = threadIdx.x;
    const int w = tid >> 5, lane = tid & 31;
    const int g = lane >> 2, tg = lane & 3;
    const int wq0 = w * 32;

    // ---- Stage all 128 Q rows (rounded): rows 0-63 -> Ks, 64-127 -> Vs ----
#pragma unroll
    for (int j = 0; j < 16; j++) {
        int i = tid + j * 128;            // 0..2047 float4 units
        int r = i >> 4, c4 = i & 15;
        float4 qv = *(const float4*)&q[(size_t)(b * TT + q0 + r) * QN + h * HD + c4 * 4];
        float* dst = (r < 64) ? &Ks[r * KST + c4 * 4] : &Vs[(r - 64) * VST + c4 * 4];
        *(float4*)dst = make_float4(rna(qv.x), rna(qv.y), rna(qv.z), rna(qv.w));
    }
    __syncthreads();

    auto qrow = [&](int r) -> const float* {
        return (r < 64) ? &Ks[r * KST] : &Vs[(r - 64) * VST];
    };

    uint32_t qfl[8][4], qfh[8][4];
#pragma unroll
    for (int ks = 0; ks < 8; ks++) {
        const int k0 = ks * 8;
        qfl[ks][0] = __float_as_uint(qrow(wq0 + g)[k0 + tg]);
        qfl[ks][1] = __float_as_uint(qrow(wq0 + g + 8)[k0 + tg]);
        qfl[ks][2] = __float_as_uint(qrow(wq0 + g)[k0 + tg + 4]);
        qfl[ks][3] = __float_as_uint(qrow(wq0 + g + 8)[k0 + tg + 4]);
        qfh[ks][0] = __float_as_uint(qrow(wq0 + 16 + g)[k0 + tg]);
        qfh[ks][1] = __float_as_uint(qrow(wq0 + 24 + g)[k0 + tg]);
        qfh[ks][2] = __float_as_uint(qrow(wq0 + 16 + g)[k0 + tg + 4]);
        qfh[ks][3] = __float_as_uint(qrow(wq0 + 24 + g)[k0 + tg + 4]);
    }

    float oal[8][4], oah[8][4];
#pragma unroll
    for (int nt = 0; nt < 8; nt++)
#pragma unroll
        for (int qq = 0; qq < 4; qq++) { oal[nt][qq] = 0.f; oah[nt][qq] = 0.f; }
    float mrow[4] = {-INFINITY, -INFINITY, -INFINITY, -INFINITY};
    float lrow[4] = {0.f, 0.f, 0.f, 0.f};

    const int nkt = 2 * qt + 2;
    for (int kt = 0; kt < nkt; ++kt) {
        __syncthreads();                 // previous iter's Ks/Vs reads done
        const int k0g = kt * 64;
        // ---- Stage K,V (rounded) ----
#pragma unroll
        for (int j = 0; j < 8; j++) {
            int i = tid + j * 128;
            int r = i >> 4, c4 = i & 15;
            size_t base = (size_t)(b * TT + k0g + r) * KN + kvh * HD + c4 * 4;
            float4 kv4 = *(const float4*)&k[base];
            float4 vv4 = *(const float4*)&v[base];
            *(float4*)&Ks[r * KST + c4 * 4] =
                make_float4(rna(kv4.x), rna(kv4.y), rna(kv4.z), rna(kv4.w));
            *(float4*)&Vs[r * VST + c4 * 4] =
                make_float4(rna(vv4.x), rna(vv4.y), rna(vv4.z), rna(vv4.w));
        }
        __syncthreads();

        // ---- S = Q @ K^T (both halves share B-frags) ----
        float scl[8][4], sch[8][4];
#pragma unroll
        for (int nt = 0; nt < 8; nt++)
#pragma unroll
            for (int qq = 0; qq < 4; qq++) { scl[nt][qq] = 0.f; sch[nt][qq] = 0.f; }

#pragma unroll
        for (int ks = 0; ks < 8; ks++) {
            const int k0 = ks * 8;
            uint32_t bf[8][2];
#pragma unroll
            for (int nt = 0; nt < 8; nt++) {
                bf[nt][0] = __float_as_uint(Ks[(nt * 8 + g) * KST + k0 + tg]);
                bf[nt][1] = __float_as_uint(Ks[(nt * 8 + g) * KST + k0 + tg + 4]);
            }
#pragma unroll
            for (int nt = 0; nt < 8; nt++) {
                mma_tf32(scl[nt], qfl[ks], bf[nt]);
                mma_tf32(sch[nt], qfh[ks], bf[nt]);
            }
        }

        // ---- scale + causal mask ----
        const float scale = 0.125f;
        if (kt >= 2 * qt) {              // diagonal region
            const int r0 = q0 + wq0 + g,      r1 = r0 + 8;
            const int r2 = q0 + wq0 + 16 + g, r3 = r2 + 8;
#pragma unroll
            for (int nt = 0; nt < 8; nt++) {
                int c0 = k0g + nt * 8 + 2 * tg, c1 = c0 + 1;
                scl[nt][0] = (c0 <= r0) ? scl[nt][0] * scale : -1e30f;
                scl[nt][1] = (c1 <= r0) ? scl[nt][1] * scale : -1e30f;
                scl[nt][2] = (c0 <= r1) ? scl[nt][2] * scale : -1e30f;
                scl[nt][3] = (c1 <= r1) ? scl[nt][3] * scale : -1e30f;
                sch[nt][0] = (c0 <= r2) ? sch[nt][0] * scale : -1e30f;
                sch[nt][1] = (c1 <= r2) ? sch[nt][1] * scale : -1e30f;
                sch[nt][2] = (c0 <= r3) ? sch[nt][2] * scale : -1e30f;
                sch[nt][3] = (c1 <= r3) ? sch[nt][3] * scale : -1e30f;
            }
        } else {
#pragma unroll
            for (int nt = 0; nt < 8; nt++)
#pragma unroll
                for (int qq = 0; qq < 4; qq++) {
                    scl[nt][qq] *= scale; sch[nt][qq] *= scale;
                }
        }

        // ---- online softmax: 4 row-sets (lo:g,g+8 ; hi:16+g,24+g) ----
        float mx[4] = {-INFINITY, -INFINITY, -INFINITY, -INFINITY};
#pragma unroll
        for (int nt = 0; nt < 8; nt++) {
            mx[0] = fmaxf(mx[0], fmaxf(scl[nt][0], scl[nt][1]));
            mx[1] = fmaxf(mx[1], fmaxf(scl[nt][2], scl[nt][3]));
            mx[2] = fmaxf(mx[2], fmaxf(sch[nt][0], sch[nt][1]));
            mx[3] = fmaxf(mx[3], fmaxf(sch[nt][2], sch[nt][3]));
        }
#pragma unroll
        for (int r = 0; r < 4; r++) {
            mx[r] = fmaxf(mx[r], __shfl_xor_sync(0xffffffffu, mx[r], 1));
            mx[r] = fmaxf(mx[r], __shfl_xor_sync(0xffffffffu, mx[r], 2));
        }
        float al[4], rs[4] = {0.f, 0.f, 0.f, 0.f};
#pragma unroll
        for (int r = 0; r < 4; r++) {
            float mn = fmaxf(mrow[r], mx[r]);
            al[r] = __expf(mrow[r] - mn);
            mrow[r] = mn;
        }
#pragma unroll
        for (int nt = 0; nt < 8; nt++) {
            scl[nt][0] = __expf(scl[nt][0] - mrow[0]);
            scl[nt][1] = __expf(scl[nt][1] - mrow[0]);
            scl[nt][2] = __expf(scl[nt][2] - mrow[1]);
            scl[nt][3] = __expf(scl[nt][3] - mrow[1]);
            sch[nt][0] = __expf(sch[nt][0] - mrow[2]);
            sch[nt][1] = __expf(sch[nt][1] - mrow[2]);
            sch[nt][2] = __expf(sch[nt][2] - mrow[3]);
            sch[nt][3] = __expf(sch[nt][3] - mrow[3]);
            rs[0] += scl[nt][0] + scl[nt][1];
            rs[1] += scl[nt][2] + scl[nt][3];
            rs[2] += sch[nt][0] + sch[nt][1];
            rs[3] += sch[nt][2] + sch[nt][3];
        }
#pragma unroll
        for (int r = 0; r < 4; r++) {
            rs[r] += __shfl_xor_sync(0xffffffffu, rs[r], 1);
            rs[r] += __shfl_xor_sync(0xffffffffu, rs[r], 2);
            lrow[r] = lrow[r] * al[r] + rs[r];
        }
#pragma unroll
        for (int nt = 0; nt < 8; nt++) {
            oal[nt][0] *= al[0]; oal[nt][1] *= al[0];
            oal[nt][2] *= al[1]; oal[nt][3] *= al[1];
            oah[nt][0] *= al[2]; oah[nt][1] *= al[2];
            oah[nt][2] *= al[3]; oah[nt][3] *= al[3];
        }

        // ---- P to smem (warp-private rows), reload as A-frags ----
#pragma unroll
        for (int nt = 0; nt < 8; nt++) {
            *(float2*)&Ps[(wq0 + g)      * KST + nt * 8 + 2 * tg] =
                make_float2(scl[nt][0], scl[nt][1]);
            *(float2*)&Ps[(wq0 + g + 8)  * KST + nt * 8 + 2 * tg] =
                make_float2(scl[nt][2], scl[nt][3]);
            *(float2*)&Ps[(wq0 + g + 16) * KST + nt * 8 + 2 * tg] =
                make_float2(sch[nt][0], sch[nt][1]);
            *(float2*)&Ps[(wq0 + g + 24) * KST + nt * 8 + 2 * tg] =
                make_float2(sch[nt][2], sch[nt][3]);
        }
        __syncwarp();

        // ---- O += P @ V (both halves share B-frags) ----
#pragma unroll
        for (int ks = 0; ks < 8; ks++) {
            const int kk = ks * 8;
            uint32_t afl[4], afh[4];
            afl[0] = __float_as_uint(Ps[(wq0 + g)      * KST + kk + tg]);
            afl[1] = __float_as_uint(Ps[(wq0 + g + 8)  * KST + kk + tg]);
            afl[2] = __float_as_uint(Ps[(wq0 + g)      * KST + kk + tg + 4]);
            afl[3] = __float_as_uint(Ps[(wq0 + g + 8)  * KST + kk + tg + 4]);
            afh[0] = __float_as_uint(Ps[(wq0 + g + 16) * KST + kk + tg]);
            afh[1] = __float_as_uint(Ps[(wq0 + g + 24) * KST + kk + tg]);
            afh[2] = __float_as_uint(Ps[(wq0 + g + 16) * KST + kk + tg + 4]);
            afh[3] = __float_as_uint(Ps[(wq0 + g + 24) * KST + kk + tg + 4]);
            uint32_t bf[8][2];
#pragma unroll
            for (int nt = 0; nt < 8; nt++) {
                bf[nt][0] = __float_as_uint(Vs[(kk + tg)     * VST + nt * 8 + g]);
                bf[nt][1] = __float_as_uint(Vs[(kk + tg + 4) * VST + nt * 8 + g]);
            }
#pragma unroll
            for (int nt = 0; nt < 8; nt++) {
                mma_tf32(oal[nt], afl, bf[nt]);
                mma_tf32(oah[nt], afh, bf[nt]);
            }
        }
    }

    // ---- normalize + write (tf32-rounded: feeds O-proj GEMM directly) ----
    float inv[4];
#pragma unroll
    for (int r = 0; r < 4; r++) inv[r] = 1.f / lrow[r];
    const int rb = b * TT + q0 + wq0 + g;
#pragma unroll
    for (int nt = 0; nt < 8; nt++) {
        const int col = h * HD + nt * 8 + 2 * tg;
        *(float2*)&o[(size_t)rb * QN + col] =
            make_float2(rna(oal[nt][0] * inv[0]), rna(oal[nt][1] * inv[0]));
        *(float2*)&o[(size_t)(rb + 8) * QN + col] =
            make_float2(rna(oal[nt][2] * inv[1]), rna(oal[nt][3] * inv[1]));
        *(float2*)&o[(size_t)(rb + 16) * QN + col] =
            make_float2(rna(oah[nt][0] * inv[2]), rna(oah[nt][1] * inv[2]));
        *(float2*)&o[(size_t)(rb + 24) * QN + col] =
            make_float2(rna(oah[nt][2] * inv[3]), rna(oah[nt][3] * inv[3]));
    }
}

// ---------------------------------------------------------------------------
// Launcher
// ---------------------------------------------------------------------------
extern "C" void kernel_launch(void* const* d_in, const int* in_sizes, int n_in,
                              void* d_out, int out_size) {
    const float* x   = (const float*)d_in[0];
    const float* cs  = (const float*)d_in[1];
    const float* sn  = (const float*)d_in[2];
    const float* Wq  = (const float*)d_in[3];
    const float* Wk  = (const float*)d_in[4];
    const float* Wv  = (const float*)d_in[5];
    const float* Wo  = (const float*)d_in[6];
    float* out = (float*)d_out;

    float *q_ptr, *k_ptr, *v_ptr, *att_ptr;
    float *xc, *wqc, *wkc, *wvc, *woc;
    cudaGetSymbolAddress((void**)&q_ptr,  g_q);
    cudaGetSymbolAddress((void**)&k_ptr,  g_k);
    cudaGetSymbolAddress((void**)&v_ptr,  g_v);
    cudaGetSymbolAddress((void**)&att_ptr, g_att);
    cudaGetSymbolAddress((void**)&xc,   g_xc);
    cudaGetSymbolAddress((void**)&wqc,  g_wqc);
    cudaGetSymbolAddress((void**)&wkc,  g_wkc);
    cudaGetSymbolAddress((void**)&wvc,  g_wvc);
    cudaGetSymbolAddress((void**)&woc,  g_woc);

    cudaFuncSetAttribute(gemm_mma, cudaFuncAttributeMaxDynamicSharedMemorySize, GEMM_SMEM);
    cudaFuncSetAttribute(attn_tc,  cudaFuncAttributeMaxDynamicSharedMemorySize, ATTN_SMEM);

    // Pre-round inputs once (numerically identical to in-loop rounding)
    {
        int n4;
        n4 = MROWS*DM/4;  cvt_tf32<<<(n4+255)/256, 256>>>(x,  xc,  n4);
        n4 = QN*DM/4;     cvt_tf32<<<(n4+255)/256, 256>>>(Wq, wqc, n4);
        n4 = KN*DM/4;     cvt_tf32<<<(n4+255)/256, 256>>>(Wk, wkc, n4);
        n4 = KN*DM/4;     cvt_tf32<<<(n4+255)/256, 256>>>(Wv, wvc, n4);
        n4 = DM*QN/4;     cvt_tf32<<<(n4+255)/256, 256>>>(Wo, woc, n4);
    }

    // Fused QKV projection: N = 2048 + 512 + 512 = 3072
    gemm_mma<<<dim3(3072/BN, MROWS/BM), 256, GEMM_SMEM>>>(
        xc, wqc, wkc, wvc, q_ptr, k_ptr, v_ptr, 2048, 2560, QN);

    // RoPE on q and k
    {
        int totq = BB * TT * NH * 32;
        rope_kernel<<<(totq + 255) / 256, 256>>>(q_ptr, cs, sn, NH, totq);
        int totk = BB * TT * NKV * 32;
        rope_kernel<<<(totk + 255) / 256, 256>>>(k_ptr, cs, sn, NKV, totk);
    }

    // Tensor-core flash attention (q-tile 128)
    attn_tc<<<dim3(TT / 128, NH, BB), 128, ATTN_SMEM>>>(q_ptr, k_ptr, v_ptr, att_ptr);

    // Output projection (seg 0 only; A = rounded attn output)
    gemm_mma<<<dim3(DM/BN, MROWS/BM), 256, GEMM_SMEM>>>(
        att_ptr, woc, woc, woc, out, out, out, DM, DM + 512, DM);
}

// round 8
// speedup vs baseline: 1.0458x; 1.0458x over previous
#include <cuda_runtime.h>
#include <cuda_bf16.h>
#include <math.h>
#include <stdint.h>

// Problem constants
#define BB 2
#define TT 2048
#define DM 2048
#define NH 32
#define NKV 8
#define HD 64
#define MROWS (BB*TT)          // 4096
#define QN (NH*HD)             // 2048
#define KN (NKV*HD)            // 512
#define GK DM                  // K dim of every GEMM = 2048

// Scratch (device globals — allocation-free)
__device__ float g_q[MROWS*QN];
__device__ float g_k[MROWS*KN];
__device__ float g_v[MROWS*KN];
__device__ float g_att[MROWS*QN];
__device__ float g_xc[MROWS*DM];
__device__ float g_wqc[QN*DM];
__device__ float g_wkc[KN*DM];
__device__ float g_wvc[KN*DM];
__device__ float g_woc[DM*QN];

__device__ __forceinline__ float rna(float x) {
    uint32_t u;
    asm("cvt.rna.tf32.f32 %0, %1;" : "=r"(u) : "f"(x));
    return __uint_as_float(u);
}
__device__ __forceinline__ uint32_t smem_u32(const void* p) {
    uint32_t a;
    asm("{ .reg .u64 t; cvta.to.shared.u64 t, %1; cvt.u32.u64 %0, t; }"
        : "=r"(a) : "l"(p));
    return a;
}
__device__ __forceinline__ void mma_tf32(float c[4], const uint32_t a[4],
                                         const uint32_t b[2]) {
    asm volatile(
        "mma.sync.aligned.m16n8k8.row.col.f32.tf32.tf32.f32 "
        "{%0,%1,%2,%3}, {%4,%5,%6,%7}, {%8,%9}, {%0,%1,%2,%3};"
        : "+f"(c[0]), "+f"(c[1]), "+f"(c[2]), "+f"(c[3])
        : "r"(a[0]), "r"(a[1]), "r"(a[2]), "r"(a[3]), "r"(b[0]), "r"(b[1]));
}

// ---------------------------------------------------------------------------
// Fused tf32 rounding pass for all 5 GEMM operands (1 launch)
// ---------------------------------------------------------------------------
#define N4_X  (MROWS*DM/4)
#define N4_WQ (QN*DM/4)
#define N4_WK (KN*DM/4)
#define N4_WV (KN*DM/4)
#define N4_WO (DM*QN/4)
#define N4_ALL (N4_X + N4_WQ + N4_WK + N4_WV + N4_WO)

__global__ void cvt_all(const float* __restrict__ x,  const float* __restrict__ wq,
                        const float* __restrict__ wk, const float* __restrict__ wv,
                        const float* __restrict__ wo,
                        float* __restrict__ xc,  float* __restrict__ wqc,
                        float* __restrict__ wkc, float* __restrict__ wvc,
                        float* __restrict__ woc) {
    int i = blockIdx.x * blockDim.x + threadIdx.x;
    if (i >= N4_ALL) return;
    const float* src; float* dst; int off;
    if (i < N4_X)                          { src = x;  dst = xc;  off = 0; }
    else if (i < N4_X + N4_WQ)             { src = wq; dst = wqc; off = N4_X; }
    else if (i < N4_X + N4_WQ + N4_WK)     { src = wk; dst = wkc; off = N4_X + N4_WQ; }
    else if (i < N4_X + N4_WQ + N4_WK + N4_WV)
                                           { src = wv; dst = wvc; off = N4_X + N4_WQ + N4_WK; }
    else                                   { src = wo; dst = woc; off = N4_X + N4_WQ + N4_WK + N4_WV; }
    int j = i - off;
    float4 v = ((const float4*)src)[j];
    ((float4*)dst)[j] = make_float4(rna(v.x), rna(v.y), rna(v.z), rna(v.w));
}

// ---------------------------------------------------------------------------
// mma.sync tf32 NT GEMM, BM=128, BN=256, BK=32, 256 threads, 3-stage cp.async.
// Segmented-N for fused QKV. rmask bit per segment: rna-round epilogue values.
// ---------------------------------------------------------------------------
#define BM 128
#define BN 256
#define BK 32
#define NCH (GK/BK)            // 64
#define RST 36
#define ATILEB (128*RST*4)
#define STAGEB ((128+256)*RST*4)   // 55296 B
#define GEMM_SMEM (3*STAGEB)       // 165888 B

__global__ __launch_bounds__(256, 1) void gemm_mma(
    const float* __restrict__ A,
    const float* __restrict__ B0, const float* __restrict__ B1,
    const float* __restrict__ B2,
    float* __restrict__ C0, float* __restrict__ C1, float* __restrict__ C2,
    int nb1, int nb2, int ld0, int rmask) {
    extern __shared__ float sm[];
    const int tid = threadIdx.x;
    const int bm = blockIdx.y * BM;
    const int bn = blockIdx.x * BN;
    const int wid = tid >> 5, lane = tid & 31;
    const int g = lane >> 2, tg = lane & 3;
    const int wm = (wid >> 2) * 64;
    const int wn = (wid & 3) * 64;

    const float* Bp; float* Cp; int nb, ldc, seg;
    if (bn < nb1)      { Bp = B0; Cp = C0; nb = bn;       ldc = ld0; seg = 0; }
    else if (bn < nb2) { Bp = B1; Cp = C1; nb = bn - nb1; ldc = 512; seg = 1; }
    else               { Bp = B2; Cp = C2; nb = bn - nb2; ldc = 512; seg = 2; }
    const bool rnd = (rmask >> seg) & 1;

    float c[4][8][4];
#pragma unroll
    for (int i = 0; i < 4; i++)
#pragma unroll
        for (int j = 0; j < 8; j++)
#pragma unroll
            for (int q = 0; q < 4; q++) c[i][j][q] = 0.f;

    const uint32_t sb = smem_u32(sm);

    auto load_chunk = [&](int kc, int s) {
        uint32_t base = sb + s * STAGEB;
#pragma unroll
        for (int j = 0; j < 12; j++) {
            int u = tid + j * 256;
            uint32_t sa;
            const float* gp;
            if (u < 1024) {
                int r = u >> 3, c16 = u & 7;
                sa = base + r * (RST*4) + c16 * 16;
                gp = A + (size_t)(bm + r) * GK + kc * BK + c16 * 4;
            } else {
                int uu = u - 1024;
                int r = uu >> 3, c16 = uu & 7;
                sa = base + ATILEB + r * (RST*4) + c16 * 16;
                gp = Bp + (size_t)(nb + r) * GK + kc * BK + c16 * 4;
            }
            asm volatile("cp.async.cg.shared.global [%0], [%1], 16;"
                         :: "r"(sa), "l"(gp));
        }
        asm volatile("cp.async.commit_group;" ::: "memory");
    };

    load_chunk(0, 0);
    load_chunk(1, 1);

    for (int t = 0; t < NCH; t++) {
        if (t + 2 < NCH) {
            load_chunk(t + 2, (t + 2) % 3);
            asm volatile("cp.async.wait_group 2;" ::: "memory");
        } else if (t + 1 < NCH) {
            asm volatile("cp.async.wait_group 1;" ::: "memory");
        } else {
            asm volatile("cp.async.wait_group 0;" ::: "memory");
        }
        __syncthreads();

        const float* Ab = sm + (t % 3) * (STAGEB/4);
        const float* Bb = Ab + ATILEB/4;
#pragma unroll
        for (int ks = 0; ks < 4; ks++) {
            const int k0 = ks * 8;
            uint32_t af[4][4], bf[8][2];
#pragma unroll
            for (int tm = 0; tm < 4; tm++) {
                const int m0 = wm + tm * 16;
                af[tm][0] = __float_as_uint(Ab[(m0 + g)     * RST + k0 + tg]);
                af[tm][1] = __float_as_uint(Ab[(m0 + g + 8) * RST + k0 + tg]);
                af[tm][2] = __float_as_uint(Ab[(m0 + g)     * RST + k0 + tg + 4]);
                af[tm][3] = __float_as_uint(Ab[(m0 + g + 8) * RST + k0 + tg + 4]);
            }
#pragma unroll
            for (int tn = 0; tn < 8; tn++) {
                const int n0 = wn + tn * 8;
                bf[tn][0] = __float_as_uint(Bb[(n0 + g) * RST + k0 + tg]);
                bf[tn][1] = __float_as_uint(Bb[(n0 + g) * RST + k0 + tg + 4]);
            }
#pragma unroll
            for (int tm = 0; tm < 4; tm++)
#pragma unroll
                for (int tn = 0; tn < 8; tn++)
                    mma_tf32(c[tm][tn], af[tm], bf[tn]);
        }
        __syncthreads();
    }

#pragma unroll
    for (int tm = 0; tm < 4; tm++) {
        const int row0 = bm + wm + tm * 16 + g;
#pragma unroll
        for (int tn = 0; tn < 8; tn++) {
            const int col = nb + wn + tn * 8 + tg * 2;
            float2 v0 = make_float2(c[tm][tn][0], c[tm][tn][1]);
            float2 v1 = make_float2(c[tm][tn][2], c[tm][tn][3]);
            if (rnd) {
                v0.x = rna(v0.x); v0.y = rna(v0.y);
                v1.x = rna(v1.x); v1.y = rna(v1.y);
            }
            *(float2*)&Cp[(size_t)row0 * ldc + col]       = v0;
            *(float2*)&Cp[(size_t)(row0 + 8) * ldc + col] = v1;
        }
    }
}

// ---------------------------------------------------------------------------
// Fused RoPE for q and k (in-place), writes tf32-rounded values
// ---------------------------------------------------------------------------
#define ROPE_TOT (BB*TT*(NH+NKV)*32)

__global__ void rope_fused(float* __restrict__ q, float* __restrict__ kk,
                           const float* __restrict__ cs, const float* __restrict__ sn) {
    int idx = blockIdx.x * blockDim.x + threadIdx.x;
    if (idx >= ROPE_TOT) return;
    int d  = idx & 31;
    int h  = (idx >> 5) % (NH + NKV);
    int bt = idx / (32 * (NH + NKV));
    int t  = bt & (TT - 1);
    float* row = (h < NH) ? q + (size_t)bt * QN + h * HD
                          : kk + (size_t)bt * KN + (h - NH) * HD;
    float x1 = row[d], x2 = row[d + 32];
    float c1 = cs[t * HD + d],      s1 = sn[t * HD + d];
    float c2 = cs[t * HD + d + 32], s2 = sn[t * HD + d + 32];
    row[d]      = rna(x1 * c1 - x2 * s1);
    row[d + 32] = rna(x2 * c2 + x1 * s2);
}

// ---------------------------------------------------------------------------
// Tensor-core flash attention v3: cp.async double-buffered K/V.
// Block: 128 threads (4 warps x 32 q-rows). Tiles: 128 q x 64 kv, HD=64.
// All inputs pre-rounded to tf32 (rope for q/k, GEMM epilogue for v).
// Smem: Kb[2][64][68], Vb[2][64][72], Ps[128][68] = 106496 B.
// ---------------------------------------------------------------------------
#define KST 68
#define VST 72
#define PST 68
#define ATTN_SMEM ((2*64*KST + 2*64*VST + 128*PST) * 4)

__global__ __launch_bounds__(128) void attn_tc(const float* __restrict__ q,
                                               const float* __restrict__ k,
                                               const float* __restrict__ v,
                                               float* __restrict__ o) {
    const int qt = (int)gridDim.x - 1 - (int)blockIdx.x;   // heavy CTAs first
    const int h  = blockIdx.y;
    const int b  = blockIdx.z;
    const int kvh = h >> 2;
    const int q0 = qt * 128;

    extern __shared__ float sm[];
    float* Kb = sm;                     // 2 x [64][KST]
    float* Vb = Kb + 2 * 64 * KST;      // 2 x [64][VST]
    float* Ps = Vb + 2 * 64 * VST;      // [128][PST] (Q staging, then P)

    const int tid = threadIdx.x;
    const int w = tid >> 5, lane = tid & 31;
    const int g = lane >> 2, tg = lane & 3;
    const int wq0 = w * 32;

    // ---- Stage all 128 Q rows into Ps (already tf32-rounded by rope) ----
#pragma unroll
    for (int j = 0; j < 16; j++) {
        int i = tid + j * 128;            // 0..2047 float4 units
        int r = i >> 4, c4 = i & 15;
        *(float4*)&Ps[r * PST + c4 * 4] =
            *(const float4*)&q[(size_t)(b * TT + q0 + r) * QN + h * HD + c4 * 4];
    }
    __syncthreads();

    uint32_t qfl[8][4], qfh[8][4];
#pragma unroll
    for (int ks = 0; ks < 8; ks++) {
        const int k0 = ks * 8;
        qfl[ks][0] = __float_as_uint(Ps[(wq0 + g)      * PST + k0 + tg]);
        qfl[ks][1] = __float_as_uint(Ps[(wq0 + g + 8)  * PST + k0 + tg]);
        qfl[ks][2] = __float_as_uint(Ps[(wq0 + g)      * PST + k0 + tg + 4]);
        qfl[ks][3] = __float_as_uint(Ps[(wq0 + g + 8)  * PST + k0 + tg + 4]);
        qfh[ks][0] = __float_as_uint(Ps[(wq0 + g + 16) * PST + k0 + tg]);
        qfh[ks][1] = __float_as_uint(Ps[(wq0 + g + 24) * PST + k0 + tg]);
        qfh[ks][2] = __float_as_uint(Ps[(wq0 + g + 16) * PST + k0 + tg + 4]);
        qfh[ks][3] = __float_as_uint(Ps[(wq0 + g + 24) * PST + k0 + tg + 4]);
    }

    // cp.async one 64-row K/V tile into stage s
    auto cp_tile = [&](int kt, int s) {
        const float* kbp = k + (size_t)(b * TT + kt * 64) * KN + kvh * HD;
        const float* vbp = v + (size_t)(b * TT + kt * 64) * KN + kvh * HD;
        float* Kd = Kb + s * 64 * KST;
        float* Vd = Vb + s * 64 * VST;
#pragma unroll
        for (int j = 0; j < 16; j++) {
            int u = tid + j * 128;        // 0..2047
            int r = (u >> 4) & 63, c4 = u & 15;
            if (u < 1024) {
                uint32_t sa = smem_u32(&Kd[r * KST + c4 * 4]);
                asm volatile("cp.async.cg.shared.global [%0], [%1], 16;"
                             :: "r"(sa), "l"(kbp + (size_t)r * KN + c4 * 4));
            } else {
                uint32_t sa = smem_u32(&Vd[r * VST + c4 * 4]);
                asm volatile("cp.async.cg.shared.global [%0], [%1], 16;"
                             :: "r"(sa), "l"(vbp + (size_t)r * KN + c4 * 4));
            }
        }
        asm volatile("cp.async.commit_group;" ::: "memory");
    };

    float oal[8][4], oah[8][4];
#pragma unroll
    for (int nt = 0; nt < 8; nt++)
#pragma unroll
        for (int qq = 0; qq < 4; qq++) { oal[nt][qq] = 0.f; oah[nt][qq] = 0.f; }
    float mrow[4] = {-INFINITY, -INFINITY, -INFINITY, -INFINITY};
    float lrow[4] = {0.f, 0.f, 0.f, 0.f};

    const int nkt = 2 * qt + 2;
    cp_tile(0, 0);

    for (int kt = 0; kt < nkt; ++kt) {
        // prefetch next tile (buffer freed by trailing __syncthreads of kt-1)
        if (kt + 1 < nkt) {
            cp_tile(kt + 1, (kt + 1) & 1);
            asm volatile("cp.async.wait_group 1;" ::: "memory");
        } else {
            asm volatile("cp.async.wait_group 0;" ::: "memory");
        }
        __syncthreads();

        const float* Ks = Kb + (kt & 1) * 64 * KST;
        const float* Vs = Vb + (kt & 1) * 64 * VST;
        const int k0g = kt * 64;

        // ---- S = Q @ K^T ----
        float scl[8][4], sch[8][4];
#pragma unroll
        for (int nt = 0; nt < 8; nt++)
#pragma unroll
            for (int qq = 0; qq < 4; qq++) { scl[nt][qq] = 0.f; sch[nt][qq] = 0.f; }

#pragma unroll
        for (int ks = 0; ks < 8; ks++) {
            const int k0 = ks * 8;
            uint32_t bf[8][2];
#pragma unroll
            for (int nt = 0; nt < 8; nt++) {
                bf[nt][0] = __float_as_uint(Ks[(nt * 8 + g) * KST + k0 + tg]);
                bf[nt][1] = __float_as_uint(Ks[(nt * 8 + g) * KST + k0 + tg + 4]);
            }
#pragma unroll
            for (int nt = 0; nt < 8; nt++) {
                mma_tf32(scl[nt], qfl[ks], bf[nt]);
                mma_tf32(sch[nt], qfh[ks], bf[nt]);
            }
        }

        // ---- scale + causal mask ----
        const float scale = 0.125f;
        if (kt >= 2 * qt) {
            const int r0 = q0 + wq0 + g,      r1 = r0 + 8;
            const int r2 = q0 + wq0 + 16 + g, r3 = r2 + 8;
#pragma unroll
            for (int nt = 0; nt < 8; nt++) {
                int c0 = k0g + nt * 8 + 2 * tg, c1 = c0 + 1;
                scl[nt][0] = (c0 <= r0) ? scl[nt][0] * scale : -1e30f;
                scl[nt][1] = (c1 <= r0) ? scl[nt][1] * scale : -1e30f;
                scl[nt][2] = (c0 <= r1) ? scl[nt][2] * scale : -1e30f;
                scl[nt][3] = (c1 <= r1) ? scl[nt][3] * scale : -1e30f;
                sch[nt][0] = (c0 <= r2) ? sch[nt][0] * scale : -1e30f;
                sch[nt][1] = (c1 <= r2) ? sch[nt][1] * scale : -1e30f;
                sch[nt][2] = (c0 <= r3) ? sch[nt][2] * scale : -1e30f;
                sch[nt][3] = (c1 <= r3) ? sch[nt][3] * scale : -1e30f;
            }
        } else {
#pragma unroll
            for (int nt = 0; nt < 8; nt++)
#pragma unroll
                for (int qq = 0; qq < 4; qq++) {
                    scl[nt][qq] *= scale; sch[nt][qq] *= scale;
                }
        }

        // ---- online softmax ----
        float mx[4] = {-INFINITY, -INFINITY, -INFINITY, -INFINITY};
#pragma unroll
        for (int nt = 0; nt < 8; nt++) {
            mx[0] = fmaxf(mx[0], fmaxf(scl[nt][0], scl[nt][1]));
            mx[1] = fmaxf(mx[1], fmaxf(scl[nt][2], scl[nt][3]));
            mx[2] = fmaxf(mx[2], fmaxf(sch[nt][0], sch[nt][1]));
            mx[3] = fmaxf(mx[3], fmaxf(sch[nt][2], sch[nt][3]));
        }
#pragma unroll
        for (int r = 0; r < 4; r++) {
            mx[r] = fmaxf(mx[r], __shfl_xor_sync(0xffffffffu, mx[r], 1));
            mx[r] = fmaxf(mx[r], __shfl_xor_sync(0xffffffffu, mx[r], 2));
        }
        float al[4], rs[4] = {0.f, 0.f, 0.f, 0.f};
#pragma unroll
        for (int r = 0; r < 4; r++) {
            float mn = fmaxf(mrow[r], mx[r]);
            al[r] = __expf(mrow[r] - mn);
            mrow[r] = mn;
        }
#pragma unroll
        for (int nt = 0; nt < 8; nt++) {
            scl[nt][0] = __expf(scl[nt][0] - mrow[0]);
            scl[nt][1] = __expf(scl[nt][1] - mrow[0]);
            scl[nt][2] = __expf(scl[nt][2] - mrow[1]);
            scl[nt][3] = __expf(scl[nt][3] - mrow[1]);
            sch[nt][0] = __expf(sch[nt][0] - mrow[2]);
            sch[nt][1] = __expf(sch[nt][1] - mrow[2]);
            sch[nt][2] = __expf(sch[nt][2] - mrow[3]);
            sch[nt][3] = __expf(sch[nt][3] - mrow[3]);
            rs[0] += scl[nt][0] + scl[nt][1];
            rs[1] += scl[nt][2] + scl[nt][3];
            rs[2] += sch[nt][0] + sch[nt][1];
            rs[3] += sch[nt][2] + sch[nt][3];
        }
#pragma unroll
        for (int r = 0; r < 4; r++) {
            rs[r] += __shfl_xor_sync(0xffffffffu, rs[r], 1);
            rs[r] += __shfl_xor_sync(0xffffffffu, rs[r], 2);
            lrow[r] = lrow[r] * al[r] + rs[r];
        }
#pragma unroll
        for (int nt = 0; nt < 8; nt++) {
            oal[nt][0] *= al[0]; oal[nt][1] *= al[0];
            oal[nt][2] *= al[1]; oal[nt][3] *= al[1];
            oah[nt][0] *= al[2]; oah[nt][1] *= al[2];
            oah[nt][2] *= al[3]; oah[nt][3] *= al[3];
        }

        // ---- P to smem (warp-private rows), reload as A-frags ----
#pragma unroll
        for (int nt = 0; nt < 8; nt++) {
            *(float2*)&Ps[(wq0 + g)      * PST + nt * 8 + 2 * tg] =
                make_float2(scl[nt][0], scl[nt][1]);
            *(float2*)&Ps[(wq0 + g + 8)  * PST + nt * 8 + 2 * tg] =
                make_float2(scl[nt][2], scl[nt][3]);
            *(float2*)&Ps[(wq0 + g + 16) * PST + nt * 8 + 2 * tg] =
                make_float2(sch[nt][0], sch[nt][1]);
            *(float2*)&Ps[(wq0 + g + 24) * PST + nt * 8 + 2 * tg] =
                make_float2(sch[nt][2], sch[nt][3]);
        }
        __syncwarp();

        // ---- O += P @ V ----
#pragma unroll
        for (int ks = 0; ks < 8; ks++) {
            const int kk = ks * 8;
            uint32_t afl[4], afh[4];
            afl[0] = __float_as_uint(Ps[(wq0 + g)      * PST + kk + tg]);
            afl[1] = __float_as_uint(Ps[(wq0 + g + 8)  * PST + kk + tg]);
            afl[2] = __float_as_uint(Ps[(wq0 + g)      * PST + kk + tg + 4]);
            afl[3] = __float_as_uint(Ps[(wq0 + g + 8)  * PST + kk + tg + 4]);
            afh[0] = __float_as_uint(Ps[(wq0 + g + 16) * PST + kk + tg]);
            afh[1] = __float_as_uint(Ps[(wq0 + g + 24) * PST + kk + tg]);
            afh[2] = __float_as_uint(Ps[(wq0 + g + 16) * PST + kk + tg + 4]);
            afh[3] = __float_as_uint(Ps[(wq0 + g + 24) * PST + kk + tg + 4]);
            uint32_t bf[8][2];
#pragma unroll
            for (int nt = 0; nt < 8; nt++) {
                bf[nt][0] = __float_as_uint(Vs[(kk + tg)     * VST + nt * 8 + g]);
                bf[nt][1] = __float_as_uint(Vs[(kk + tg + 4) * VST + nt * 8 + g]);
            }
#pragma unroll
            for (int nt = 0; nt < 8; nt++) {
                mma_tf32(oal[nt], afl, bf[nt]);
                mma_tf32(oah[nt], afh, bf[nt]);
            }
        }
        __syncthreads();   // all warps done with this K/V buffer
    }

    // ---- normalize + write (tf32-rounded: feeds O-proj GEMM directly) ----
    float inv[4];
#pragma unroll
    for (int r = 0; r < 4; r++) inv[r] = 1.f / lrow[r];
    const int rb = b * TT + q0 + wq0 + g;
#pragma unroll
    for (int nt = 0; nt < 8; nt++) {
        const int col = h * HD + nt * 8 + 2 * tg;
        *(float2*)&o[(size_t)rb * QN + col] =
            make_float2(rna(oal[nt][0] * inv[0]), rna(oal[nt][1] * inv[0]));
        *(float2*)&o[(size_t)(rb + 8) * QN + col] =
            make_float2(rna(oal[nt][2] * inv[1]), rna(oal[nt][3] * inv[1]));
        *(float2*)&o[(size_t)(rb + 16) * QN + col] =
            make_float2(rna(oah[nt][0] * inv[2]), rna(oah[nt][1] * inv[2]));
        *(float2*)&o[(size_t)(rb + 24) * QN + col] =
            make_float2(rna(oah[nt][2] * inv[3]), rna(oah[nt][3] * inv[3]));
    }
}

// ---------------------------------------------------------------------------
// Launcher
// ---------------------------------------------------------------------------
extern "C" void kernel_launch(void* const* d_in, const int* in_sizes, int n_in,
                              void* d_out, int out_size) {
    const float* x   = (const float*)d_in[0];
    const float* cs  = (const float*)d_in[1];
    const float* sn  = (const float*)d_in[2];
    const float* Wq  = (const float*)d_in[3];
    const float* Wk  = (const float*)d_in[4];
    const float* Wv  = (const float*)d_in[5];
    const float* Wo  = (const float*)d_in[6];
    float* out = (float*)d_out;

    float *q_ptr, *k_ptr, *v_ptr, *att_ptr;
    float *xc, *wqc, *wkc, *wvc, *woc;
    cudaGetSymbolAddress((void**)&q_ptr,  g_q);
    cudaGetSymbolAddress((void**)&k_ptr,  g_k);
    cudaGetSymbolAddress((void**)&v_ptr,  g_v);
    cudaGetSymbolAddress((void**)&att_ptr, g_att);
    cudaGetSymbolAddress((void**)&xc,   g_xc);
    cudaGetSymbolAddress((void**)&wqc,  g_wqc);
    cudaGetSymbolAddress((void**)&wkc,  g_wkc);
    cudaGetSymbolAddress((void**)&wvc,  g_wvc);
    cudaGetSymbolAddress((void**)&woc,  g_woc);

    cudaFuncSetAttribute(gemm_mma, cudaFuncAttributeMaxDynamicSharedMemorySize, GEMM_SMEM);
    cudaFuncSetAttribute(attn_tc,  cudaFuncAttributeMaxDynamicSharedMemorySize, ATTN_SMEM);

    // 1) Pre-round all GEMM operands (single launch)
    cvt_all<<<(N4_ALL + 255) / 256, 256>>>(x, Wq, Wk, Wv, Wo,
                                           xc, wqc, wkc, wvc, woc);

    // 2) Fused QKV projection: N = 2048 + 512 + 512; round V segment (bit 2)
    gemm_mma<<<dim3(3072/BN, MROWS/BM), 256, GEMM_SMEM>>>(
        xc, wqc, wkc, wvc, q_ptr, k_ptr, v_ptr, 2048, 2560, QN, 0b100);

    // 3) Fused RoPE on q and k (writes tf32-rounded)
    rope_fused<<<(ROPE_TOT + 255) / 256, 256>>>(q_ptr, k_ptr, cs, sn);

    // 4) Tensor-core flash attention (q-tile 128, cp.async double-buffered)
    attn_tc<<<dim3(TT / 128, NH, BB), 128, ATTN_SMEM>>>(q_ptr, k_ptr, v_ptr, att_ptr);

    // 5) Output projection (seg 0 only; no epilogue rounding)
    gemm_mma<<<dim3(DM/BN, MROWS/BM), 256, GEMM_SMEM>>>(
        att_ptr, woc, woc, woc, out, out, out, DM, DM + 512, DM, 0);
}